// round 1
// baseline (speedup 1.0000x reference)
#include <cuda_runtime.h>
#include <stdint.h>

// Problem constants (from reference)
#define BB 16
#define NN 8192
#define DD 256
#define HH 128
#define NP 64
#define KSEL 32
#define ROWS (BB * NN)          // 131072
#define SEL_PER_B (NP * KSEL)   // 2048

typedef unsigned long long ull;

// ---- packed f32x2 helpers (Blackwell) ----
__device__ __forceinline__ ull pack2(float x, float y) {
    ull r;
    asm("mov.b64 %0, {%1, %2};" : "=l"(r) : "f"(x), "f"(y));
    return r;
}
__device__ __forceinline__ void unpack2(ull v, float& lo, float& hi) {
    asm("mov.b64 {%0, %1}, %2;" : "=f"(lo), "=f"(hi) : "l"(v));
}
__device__ __forceinline__ void fma2(ull& c, ull a, ull b) {
    asm("fma.rn.f32x2 %0, %1, %2, %3;" : "=l"(c) : "l"(a), "l"(b), "l"(c));
}

// ============================================================
// K1: logits[r] = relu(features[r,:] @ W1 + b1) @ W2 + b2
// Tiled fp32 GEMM, 128 rows x 128 hidden per block, f32x2 FMA.
// ============================================================
#define TM 128
#define KT 32
#define LDA 132
#define LDB 132

__global__ __launch_bounds__(256, 2)
void k_logits(const float* __restrict__ features,
              const float* __restrict__ W1,
              const float* __restrict__ b1,
              const float* __restrict__ W2,
              const float* __restrict__ b2,
              float* __restrict__ logits)
{
    __shared__ __align__(16) float As[KT][LDA];  // As[k][m] = features[row0+m][kt+k]
    __shared__ __align__(16) float Bs[KT][LDB];  // Bs[k][h] = W1[kt+k][h]

    const int tid = threadIdx.x;
    const int tx = tid & 15;      // hidden group: h = tx*8 .. +7
    const int ty = tid >> 4;      // row group:    m = ty*8 .. +7
    const int row0 = blockIdx.x * TM;

    // c2[i2][j]: .lo = c[2*i2][j], .hi = c[2*i2+1][j]
    ull c2[4][8];
#pragma unroll
    for (int i = 0; i < 4; i++)
#pragma unroll
        for (int j = 0; j < 8; j++) c2[i][j] = 0ULL;  // bits of {0.f, 0.f}

    for (int kt = 0; kt < DD; kt += KT) {
        // Load A tile (128 x 32), transposed into As[k][m]
#pragma unroll
        for (int i = 0; i < 4; i++) {
            int idx = tid + 256 * i;           // 0..1023 float4 slots
            int m = idx >> 3;                  // row within tile
            int k4 = idx & 7;                  // float4 index along k
            float4 v = *(const float4*)&features[(size_t)(row0 + m) * DD + kt + k4 * 4];
            As[k4 * 4 + 0][m] = v.x;
            As[k4 * 4 + 1][m] = v.y;
            As[k4 * 4 + 2][m] = v.z;
            As[k4 * 4 + 3][m] = v.w;
        }
        // Load B tile (32 x 128), direct copy (W1 is already k-major)
#pragma unroll
        for (int i = 0; i < 4; i++) {
            int idx = tid + 256 * i;
            int k = idx >> 5;
            int h4 = idx & 31;
            *(float4*)&Bs[k][h4 * 4] = *(const float4*)&W1[(size_t)(kt + k) * HH + h4 * 4];
        }
        __syncthreads();

#pragma unroll
        for (int k = 0; k < KT; k++) {
            ull a2[4];
#pragma unroll
            for (int i2 = 0; i2 < 4; i2++)
                a2[i2] = *(const ull*)&As[k][ty * 8 + i2 * 2];
            float4 bl = *(const float4*)&Bs[k][tx * 8];
            float4 bh = *(const float4*)&Bs[k][tx * 8 + 4];
            ull bd[8];
            bd[0] = pack2(bl.x, bl.x); bd[1] = pack2(bl.y, bl.y);
            bd[2] = pack2(bl.z, bl.z); bd[3] = pack2(bl.w, bl.w);
            bd[4] = pack2(bh.x, bh.x); bd[5] = pack2(bh.y, bh.y);
            bd[6] = pack2(bh.z, bh.z); bd[7] = pack2(bh.w, bh.w);
#pragma unroll
            for (int i2 = 0; i2 < 4; i2++)
#pragma unroll
                for (int j = 0; j < 8; j++)
                    fma2(c2[i2][j], a2[i2], bd[j]);
        }
        __syncthreads();
    }

    // Epilogue: relu(c + b1) * W2, reduce over hidden (tx groups of 16 lanes)
    float part[8];
#pragma unroll
    for (int i = 0; i < 8; i++) part[i] = 0.0f;

#pragma unroll
    for (int j = 0; j < 8; j++) {
        int h = tx * 8 + j;
        float bb = __ldg(&b1[h]);
        float w  = __ldg(&W2[h]);
#pragma unroll
        for (int i2 = 0; i2 < 4; i2++) {
            float lo, hi;
            unpack2(c2[i2][j], lo, hi);
            float v0 = lo + bb; v0 = v0 > 0.0f ? v0 : 0.0f;
            float v1 = hi + bb; v1 = v1 > 0.0f ? v1 : 0.0f;
            part[2 * i2 + 0] += v0 * w;
            part[2 * i2 + 1] += v1 * w;
        }
    }

    // Reduce over the 16 tx-lanes (lanes within warp are consecutive in tx)
#pragma unroll
    for (int off = 8; off; off >>= 1)
#pragma unroll
        for (int i = 0; i < 8; i++)
            part[i] += __shfl_xor_sync(0xFFFFFFFFu, part[i], off, 16);

    if (tx == 0) {
        float bb2 = __ldg(b2);
#pragma unroll
        for (int i = 0; i < 8; i++)
            logits[(size_t)row0 + ty * 8 + i] = part[i] + bb2;
    }
}

// ============================================================
// K2: per (batch, parcel) top-32 of z = logits + gumbel over the
// 128 candidates n = p + 64*i. Descending, ties -> lower index.
// One warp per (b, p); 1024 warps total.
// ============================================================
__global__ void k_select(const float* __restrict__ logits,
                         const float* __restrict__ gumbel,
                         float* __restrict__ out_idx)
{
    const int g = blockIdx.x * (blockDim.x >> 5) + (threadIdx.x >> 5);
    const int lane = threadIdx.x & 31;
    const int b = g >> 6;
    const int p = g & 63;
    const float NEG_INF = __int_as_float(0xff800000);

    float v[4];
    int nidx[4];
#pragma unroll
    for (int q = 0; q < 4; q++) {
        int n = p + 64 * (lane + 32 * q);
        size_t off = (size_t)b * NN + n;
        v[q] = logits[off] + gumbel[off];
        nidx[q] = n;
    }

    for (int it = 0; it < KSEL; it++) {
        float bv = v[0]; int bn = nidx[0];
#pragma unroll
        for (int q = 1; q < 4; q++) {
            if (v[q] > bv || (v[q] == bv && nidx[q] < bn)) { bv = v[q]; bn = nidx[q]; }
        }
#pragma unroll
        for (int off = 16; off; off >>= 1) {
            float ov = __shfl_xor_sync(0xFFFFFFFFu, bv, off);
            int   on = __shfl_xor_sync(0xFFFFFFFFu, bn, off);
            if (ov > bv || (ov == bv && on < bn)) { bv = ov; bn = on; }
        }
        if (lane == 0)
            out_idx[(size_t)b * SEL_PER_B + p * KSEL + it] = (float)bn;
#pragma unroll
        for (int q = 0; q < 4; q++)
            if (nidx[q] == bn) v[q] = NEG_INF;
    }
}

// ============================================================
// K3: selected_patches[b, j, :] = patches[b, idx[b,j], :]
// One block (64 threads) per output row; float4 copies.
// ============================================================
__global__ void k_gather(const float* __restrict__ patches,
                         const float* __restrict__ out_idx,
                         float* __restrict__ out_sel)
{
    const int blk = blockIdx.x;             // 0 .. B*2048-1
    const int b = blk >> 11;
    const int j = blk & 2047;
    const int n = (int)out_idx[(size_t)b * SEL_PER_B + j];
    const float4* src = (const float4*)&patches[((size_t)b * NN + n) * DD];
    float4* dst = (float4*)&out_sel[((size_t)b * SEL_PER_B + j) * DD];
    dst[threadIdx.x] = src[threadIdx.x];
}

// ============================================================
// launch
// ============================================================
extern "C" void kernel_launch(void* const* d_in, const int* in_sizes, int n_in,
                              void* d_out, int out_size)
{
    const float* patches  = (const float*)d_in[0];
    const float* features = (const float*)d_in[1];
    const float* W1       = (const float*)d_in[2];
    const float* b1       = (const float*)d_in[3];
    const float* W2       = (const float*)d_in[4];
    const float* b2       = (const float*)d_in[5];
    const float* gumbel   = (const float*)d_in[6];
    // d_in[7] = lookup: arange(N) % 64 (pattern exploited directly in k_select)

    float* out      = (float*)d_out;
    float* out_sel  = out;                                         // [B, 2048, 256]
    float* out_idx  = out + (size_t)BB * SEL_PER_B * DD;           // [B, 2048]
    float* out_log  = out_idx + (size_t)BB * SEL_PER_B;            // [B, N]

    k_logits<<<ROWS / TM, 256>>>(features, W1, b1, W2, b2, out_log);
    k_select<<<(BB * NP) / 8, 256>>>(out_log, gumbel, out_idx);
    k_gather<<<BB * SEL_PER_B, 64>>>(patches, out_idx, out_sel);
}